// round 4
// baseline (speedup 1.0000x reference)
#include <cuda_runtime.h>

// LIF activation recurrence, float4-vectorized:
//   keep = (Vm < 1) ? Vm : 0
//   Vm   = relu(x_t + (1 - w_leak) * keep)
//   out  = (Vm > 1) ? 1 : 0
// x: [B=128, T=1000, C=512] f32, w_leak: [C] f32, out: [B, T, C] f32.
// Each thread owns 4 consecutive channels -> LDG.128/STG.128, 4 independent
// recurrence chains. 16384 threads, 32-thread blocks -> 512 blocks (3-4/SM).

#define LIF_B 128
#define LIF_T 1000
#define LIF_C 512
#define LIF_U 8        // prefetch depth (float4 timesteps per buffer)
#define LIF_C4 (LIF_C / 4)   // 128 float4 groups per row

__device__ __forceinline__ float lif_step(float& vm, float wl, float xv) {
    float vk = (vm < 1.0f) ? vm : 0.0f;                       // hard-reset gate
    vm = fmaxf(__fadd_rn(xv, __fmul_rn(wl, vk)), 0.0f);       // relu, unfused mul+add
    return (vm > 1.0f) ? 1.0f : 0.0f;                         // spike
}

__device__ __forceinline__ float4 lif_step4(float4& vm, const float4 wl, const float4 xv) {
    float4 s;
    s.x = lif_step(vm.x, wl.x, xv.x);
    s.y = lif_step(vm.y, wl.y, xv.y);
    s.z = lif_step(vm.z, wl.z, xv.z);
    s.w = lif_step(vm.w, wl.w, xv.w);
    return s;
}

__global__ __launch_bounds__(32)
void lif_kernel(const float4* __restrict__ x,
                const float4* __restrict__ w_leak,
                float4* __restrict__ out) {
    const int i  = blockIdx.x * blockDim.x + threadIdx.x;  // 0 .. 16383
    const int c4 = i & (LIF_C4 - 1);
    const int b  = i >> 7;  // log2(C4) = 7

    float4 wlv = w_leak[c4];
    wlv.x = 1.0f - wlv.x; wlv.y = 1.0f - wlv.y;
    wlv.z = 1.0f - wlv.z; wlv.w = 1.0f - wlv.w;

    const size_t base = (size_t)b * LIF_T * LIF_C4 + c4;
    const float4* xp = x + base;
    float4*       op = out + base;

    float4 vm = make_float4(0.0f, 0.0f, 0.0f, 0.0f);

    // Two fixed-name register buffers (no dynamic indexing -> no spill).
    float4 bufA[LIF_U], bufB[LIF_U];

    // Prime buffer A with t = 0..U-1
    #pragma unroll
    for (int u = 0; u < LIF_U; u++) bufA[u] = __ldcs(xp + u * LIF_C4);

    // Main loop: 62 iterations x 16 timesteps = t 0..991.
    #pragma unroll 1
    for (int t = 0; t < LIF_T - LIF_U; t += 2 * LIF_U) {
        // prefetch t+U .. t+2U-1 into B
        #pragma unroll
        for (int u = 0; u < LIF_U; u++)
            bufB[u] = __ldcs(xp + (size_t)(t + LIF_U + u) * LIF_C4);

        // compute t .. t+U-1 from A
        #pragma unroll
        for (int u = 0; u < LIF_U; u++)
            __stcs(op + (size_t)(t + u) * LIF_C4, lif_step4(vm, wlv, bufA[u]));

        // prefetch t+2U .. t+3U-1 into A (last iter loads t=992..999)
        #pragma unroll
        for (int u = 0; u < LIF_U; u++)
            bufA[u] = __ldcs(xp + (size_t)(t + 2 * LIF_U + u) * LIF_C4);

        // compute t+U .. t+2U-1 from B
        #pragma unroll
        for (int u = 0; u < LIF_U; u++)
            __stcs(op + (size_t)(t + LIF_U + u) * LIF_C4, lif_step4(vm, wlv, bufB[u]));
    }

    // Tail: t = 992..999 already in bufA from the last prefetch.
    #pragma unroll
    for (int u = 0; u < LIF_U; u++)
        __stcs(op + (size_t)(LIF_T - LIF_U + u) * LIF_C4, lif_step4(vm, wlv, bufA[u]));
}

extern "C" void kernel_launch(void* const* d_in, const int* in_sizes, int n_in,
                              void* d_out, int out_size) {
    const float4* x      = (const float4*)d_in[0];   // [B, T, C] f32
    const float4* w_leak = (const float4*)d_in[1];   // [C] f32
    float4* out = (float4*)d_out;                    // [B, T, C] f32

    const int total = LIF_B * LIF_C4;                // 16384 threads
    lif_kernel<<<total / 32, 32>>>(x, w_leak, out);
}

// round 7
// speedup vs baseline: 1.4366x; 1.4366x over previous
#include <cuda_runtime.h>

// LIF activation recurrence (scalar lanes, deep double-buffered prefetch):
//   keep = (Vm < 1) ? Vm : 0
//   Vm   = relu(x_t + (1 - w_leak) * keep)
//   out  = (Vm > 1) ? 1 : 0
// x: [B=128, T=1000, C=512] f32, w_leak: [C] f32, out: [B, T, C] f32.
// One thread per (b,c) lane: 65536 threads = 2048 warps (~13.8/SM), perfectly
// coalesced 128B/warp per timestep. U=20 prefetch depth -> ~35KB reads in
// flight per SM (covers DRAM latency x bandwidth product ~25KB).

#define LIF_B 128
#define LIF_T 1000
#define LIF_C 512
#define LIF_U 20                 // prefetch depth per buffer; 1000 = 20 + 24*40 + 40-20
#define LIF_BLOCK 64

__device__ __forceinline__ float lif_step(float& vm, float wl, float xv) {
    float vk = (vm < 1.0f) ? vm : 0.0f;                       // hard-reset gate
    vm = fmaxf(__fadd_rn(xv, __fmul_rn(wl, vk)), 0.0f);       // relu, unfused mul+add
    return (vm > 1.0f) ? 1.0f : 0.0f;                         // spike
}

__global__ __launch_bounds__(LIF_BLOCK)
void lif_kernel(const float* __restrict__ x,
                const float* __restrict__ w_leak,
                float* __restrict__ out) {
    const int i = blockIdx.x * LIF_BLOCK + threadIdx.x;  // 0 .. B*C-1
    const int c = i & (LIF_C - 1);
    const int b = i >> 9;                                // log2(C) = 9

    const float wl = 1.0f - w_leak[c];
    const size_t base = (size_t)b * LIF_T * LIF_C + c;
    const float* xp = x + base;
    float*       op = out + base;

    float vm = 0.0f;

    // Two fixed-name register buffers (no dynamic indexing -> no spill).
    float bufA[LIF_U], bufB[LIF_U];

    // Prime buffer A with t = 0..19
    #pragma unroll
    for (int u = 0; u < LIF_U; u++)
        bufA[u] = __ldcs(xp + (size_t)u * LIF_C);

    // Main loop: 24 iterations x 40 timesteps, t = 0..919 start points.
    // Last iteration (t=920) prefetches A from 960..979 -- in bounds.
    #pragma unroll 1
    for (int t = 0; t <= LIF_T - 2 * LIF_U - 40; t += 2 * LIF_U) {
        // prefetch t+20 .. t+39 into B
        #pragma unroll
        for (int u = 0; u < LIF_U; u++)
            bufB[u] = __ldcs(xp + (size_t)(t + LIF_U + u) * LIF_C);

        // compute t .. t+19 from A
        #pragma unroll
        for (int u = 0; u < LIF_U; u++)
            __stcs(op + (size_t)(t + u) * LIF_C, lif_step(vm, wl, bufA[u]));

        // prefetch t+40 .. t+59 into A
        #pragma unroll
        for (int u = 0; u < LIF_U; u++)
            bufA[u] = __ldcs(xp + (size_t)(t + 2 * LIF_U + u) * LIF_C);

        // compute t+20 .. t+39 from B
        #pragma unroll
        for (int u = 0; u < LIF_U; u++)
            __stcs(op + (size_t)(t + LIF_U + u) * LIF_C, lif_step(vm, wl, bufB[u]));
    }

    // Tail: computed through t=959; bufA holds 960..979. Load 980..999, finish.
    #pragma unroll
    for (int u = 0; u < LIF_U; u++)
        bufB[u] = __ldcs(xp + (size_t)(LIF_T - LIF_U + u) * LIF_C);

    #pragma unroll
    for (int u = 0; u < LIF_U; u++)
        __stcs(op + (size_t)(LIF_T - 2 * LIF_U + u) * LIF_C, lif_step(vm, wl, bufA[u]));

    #pragma unroll
    for (int u = 0; u < LIF_U; u++)
        __stcs(op + (size_t)(LIF_T - LIF_U + u) * LIF_C, lif_step(vm, wl, bufB[u]));
}

extern "C" void kernel_launch(void* const* d_in, const int* in_sizes, int n_in,
                              void* d_out, int out_size) {
    const float* x      = (const float*)d_in[0];   // [B, T, C] f32
    const float* w_leak = (const float*)d_in[1];   // [C] f32
    float* out = (float*)d_out;                    // [B, T, C] f32

    const int total = LIF_B * LIF_C;               // 65536 lanes
    lif_kernel<<<total / LIF_BLOCK, LIF_BLOCK>>>(x, w_leak, out);
}